// round 12
// baseline (speedup 1.0000x reference)
#include <cuda_runtime.h>
#include <math.h>

#define BB 32
#define DIN 1024
#define DOUT 1024
#define BETA 0.9f
#define LEAK 0.9f

#define GRIDN 512
#define NTHR 256

#define KTILE 16
#define NSPLIT (DIN / KTILE)   /* 64 */
#define NJT 8                  /* j tiles of 128 */

/* output offsets (floats), in reference return order:
   s, E_W2, E_b2, Rh_W2, Rh_b2, g_bar2, r2 */
#define OFF_S  0
#define OFF_EW (BB * DOUT)
#define OFF_EB (OFF_EW + BB * DIN * DOUT)
#define OFF_RW (OFF_EB + BB * DOUT)
#define OFF_RB (OFF_RW + BB * DIN * DOUT)
#define OFF_G  (OFF_RB + BB * DOUT)
#define OFF_R  (OFF_G + BB * DOUT)

#define NVEC (BB * DIN * DOUT / 4)      /* 8388608 float4 elements */
#define STRIDE (GRIDN * NTHR)           /* 131072 */
#define HALF (NVEC / 2)                 /* 4194304 */
#define NITER (HALF / STRIDE)           /* 32 */

__device__ float g_hpart[NSPLIT][BB * DOUT];   /* 8 MB scratch */
__device__ unsigned int g_c1, g_c2;            /* monotonic barrier counters */

/* wrap-safe, reset-free grid barrier: counter only ever increments; each
   launch consumes exactly GRIDN increments per counter, so the target is
   (prev rounded down to a multiple of GRIDN) + GRIDN. 2^32 % 512 == 0. */
__device__ __forceinline__ void grid_sync(unsigned int* cnt) {
    __syncthreads();
    if (threadIdx.x == 0) {
        __threadfence();
        const unsigned int prev = atomicAdd(cnt, 1u);
        const unsigned int target = prev - (prev % GRIDN) + GRIDN;
        volatile unsigned int* vc = (volatile unsigned int*)cnt;
        while ((int)(*vc - target) < 0) { __nanosleep(64); }
        __threadfence();
    }
    __syncthreads();
}

__global__ void __launch_bounds__(NTHR, 4)
fused_all(const float* __restrict__ x,
          const float* __restrict__ W,
          const float* __restrict__ bias,
          const float* __restrict__ u,
          const float4* __restrict__ E_W,
          const float* __restrict__ E_b,
          const float4* __restrict__ Rh_W,
          const float* __restrict__ Rh_b,
          const float* __restrict__ g_bar,
          const float* __restrict__ r,
          float* __restrict__ out) {
    __shared__ float ws[KTILE][128];   /* 8 KB: W tile 16k x 128j */
    __shared__ float xs[BB][KTILE];    /* 2 KB: x tile 32b x 16k */

    const int bid = blockIdx.x;
    const int tid = threadIdx.x;

    /* ================= Phase A: split-K GEMM ================= */
    {
        const int jt = bid & 7;          /* j tile: 128 columns */
        const int ks = bid >> 3;         /* k split: 16 rows */
        const int k0 = ks * KTILE;
        const int jb = jt * 128;

        /* W tile: 512 float4, 2 per thread */
        {
            int f = tid;
            int row = f >> 5, c4 = (f & 31) * 4;
            *(float4*)&ws[row][c4] = *(const float4*)&W[(k0 + row) * DOUT + jb + c4];
            f = tid + 256;
            row = f >> 5; c4 = (f & 31) * 4;
            *(float4*)&ws[row][c4] = *(const float4*)&W[(k0 + row) * DOUT + jb + c4];
        }
        /* x tile: 128 float4, 1 per thread (tid < 128) */
        if (tid < 128) {
            const int bb = tid >> 2;
            const int kq = (tid & 3) * 4;
            const float4 v = *(const float4*)&x[bb * DIN + k0 + kq];
            xs[bb][kq + 0] = v.x;
            xs[bb][kq + 1] = v.y;
            xs[bb][kq + 2] = v.z;
            xs[bb][kq + 3] = v.w;
        }
        __syncthreads();

        const int j4l = (tid & 31) * 4;  /* this thread's 4 j columns in tile */
        const int bq  = tid >> 5;        /* batch quad 0..7 */

        float4 a0 = make_float4(0.f, 0.f, 0.f, 0.f);
        float4 a1 = a0, a2 = a0, a3 = a0;

#pragma unroll
        for (int kk = 0; kk < KTILE; kk++) {
            const float4 w = *(const float4*)&ws[kk][j4l];
            const float x0 = xs[bq * 4 + 0][kk];
            const float x1 = xs[bq * 4 + 1][kk];
            const float x2 = xs[bq * 4 + 2][kk];
            const float x3 = xs[bq * 4 + 3][kk];
            a0.x = fmaf(x0, w.x, a0.x); a0.y = fmaf(x0, w.y, a0.y);
            a0.z = fmaf(x0, w.z, a0.z); a0.w = fmaf(x0, w.w, a0.w);
            a1.x = fmaf(x1, w.x, a1.x); a1.y = fmaf(x1, w.y, a1.y);
            a1.z = fmaf(x1, w.z, a1.z); a1.w = fmaf(x1, w.w, a1.w);
            a2.x = fmaf(x2, w.x, a2.x); a2.y = fmaf(x2, w.y, a2.y);
            a2.z = fmaf(x2, w.z, a2.z); a2.w = fmaf(x2, w.w, a2.w);
            a3.x = fmaf(x3, w.x, a3.x); a3.y = fmaf(x3, w.y, a3.y);
            a3.z = fmaf(x3, w.z, a3.z); a3.w = fmaf(x3, w.w, a3.w);
        }

        float* dst = &g_hpart[ks][0];
        *(float4*)&dst[(bq * 4 + 0) * DOUT + jb + j4l] = a0;
        *(float4*)&dst[(bq * 4 + 1) * DOUT + jb + j4l] = a1;
        *(float4*)&dst[(bq * 4 + 2) * DOUT + jb + j4l] = a2;
        *(float4*)&dst[(bq * 4 + 3) * DOUT + jb + j4l] = a3;
    }

    grid_sync(&g_c1);

    /* ================= Phase B: activation + small outputs ================= */
    if (tid < 16) {
        const int idx4 = bid * 16 + tid;      /* 0..8191 */
        const int bb = idx4 >> 8;
        const int j4 = idx4 & 255;

        float4 h = ((const float4*)bias)[j4];
#pragma unroll 8
        for (int ks = 0; ks < NSPLIT; ks++) {
            const float4 p = __ldcg(&((const float4*)g_hpart[ks])[idx4]);
            h.x += p.x; h.y += p.y; h.z += p.z; h.w += p.w;
        }

        const float4 uu = ((const float4*)u)[idx4];
        const float4 eb = ((const float4*)E_b)[idx4];
        const float4 rb = ((const float4*)Rh_b)[idx4];
        const float4 gb = ((const float4*)g_bar)[idx4];

        const float ratio0 = LEAK * r[bb];
        const float r2 = ratio0 + 1.0f;
        const float ratio = ratio0 / r2;

        float4 so, ebo, rbo, go;
        {
            const float un = BETA * uu.x + h.x;
            const float s  = 1.0f / (1.0f + expf(-(un - 1.0f)));
            const float sg = s * (1.0f - s);
            const float a  = BETA * sg;
            so.x = s;
            const float eb1 = BETA * eb.x + 1.0f;
            ebo.x = BETA * eb1 + 1.0f;
            rbo.x = a * rb.x + (a * eb1 + sg);
            go.x  = ratio * gb.x + (1.0f - ratio) * a;
        }
        {
            const float un = BETA * uu.y + h.y;
            const float s  = 1.0f / (1.0f + expf(-(un - 1.0f)));
            const float sg = s * (1.0f - s);
            const float a  = BETA * sg;
            so.y = s;
            const float eb1 = BETA * eb.y + 1.0f;
            ebo.y = BETA * eb1 + 1.0f;
            rbo.y = a * rb.y + (a * eb1 + sg);
            go.y  = ratio * gb.y + (1.0f - ratio) * a;
        }
        {
            const float un = BETA * uu.z + h.z;
            const float s  = 1.0f / (1.0f + expf(-(un - 1.0f)));
            const float sg = s * (1.0f - s);
            const float a  = BETA * sg;
            so.z = s;
            const float eb1 = BETA * eb.z + 1.0f;
            ebo.z = BETA * eb1 + 1.0f;
            rbo.z = a * rb.z + (a * eb1 + sg);
            go.z  = ratio * gb.z + (1.0f - ratio) * a;
        }
        {
            const float un = BETA * uu.w + h.w;
            const float s  = 1.0f / (1.0f + expf(-(un - 1.0f)));
            const float sg = s * (1.0f - s);
            const float a  = BETA * sg;
            so.w = s;
            const float eb1 = BETA * eb.w + 1.0f;
            ebo.w = BETA * eb1 + 1.0f;
            rbo.w = a * rb.w + (a * eb1 + sg);
            go.w  = ratio * gb.w + (1.0f - ratio) * a;
        }

        ((float4*)(out + OFF_S))[idx4]  = so;
        ((float4*)(out + OFF_EB))[idx4] = ebo;
        ((float4*)(out + OFF_RB))[idx4] = rbo;
        ((float4*)(out + OFF_G))[idx4]  = go;
        if (j4 == 0) out[OFF_R + bb] = r2;
    }

    grid_sync(&g_c2);

    /* ================= Phase C: big streaming trace update ================= */
    {
        const float4* __restrict__ s4p = (const float4*)(out + OFF_S);
        float4* __restrict__ ew2 = (float4*)(out + OFF_EW);
        float4* __restrict__ rw2 = (float4*)(out + OFF_RW);

        const int base = bid * NTHR + tid;

#pragma unroll 1
        for (int it = 0; it < NITER; it++) {
            const int idx0 = it * STRIDE + base;
            const int idx1 = idx0 + HALF;

            /* 4 independent DRAM stream loads in flight */
            const float4 ew0 = __ldcs(&E_W[idx0]);
            const float4 rh0 = __ldcs(&Rh_W[idx0]);
            const float4 ew1 = __ldcs(&E_W[idx1]);
            const float4 rh1 = __ldcs(&Rh_W[idx1]);

            const int bb0 = idx0 >> 18, rem0 = idx0 & 262143;
            const int i0 = rem0 >> 8, j40 = rem0 & 255;
            const int bb1 = idx1 >> 18, rem1 = idx1 & 262143;
            const int i1 = rem1 >> 8, j41 = rem1 & 255;

            const float  xv0 = __ldg(&x[bb0 * DIN + i0]);
            const float4 s40 = s4p[bb0 * 256 + j40];
            const float  xv1 = __ldg(&x[bb1 * DIN + i1]);
            const float4 s41 = s4p[bb1 * 256 + j41];

            float4 o1, o2;
            {
                const float sg = s40.x * (1.0f - s40.x);
                const float a  = BETA * sg;
                const float e1 = fmaf(BETA, ew0.x, xv0);
                o1.x = fmaf(BETA, e1, xv0);
                o2.x = fmaf(a, rh0.x, fmaf(a, e1, xv0 * sg));
            }
            {
                const float sg = s40.y * (1.0f - s40.y);
                const float a  = BETA * sg;
                const float e1 = fmaf(BETA, ew0.y, xv0);
                o1.y = fmaf(BETA, e1, xv0);
                o2.y = fmaf(a, rh0.y, fmaf(a, e1, xv0 * sg));
            }
            {
                const float sg = s40.z * (1.0f - s40.z);
                const float a  = BETA * sg;
                const float e1 = fmaf(BETA, ew0.z, xv0);
                o1.z = fmaf(BETA, e1, xv0);
                o2.z = fmaf(a, rh0.z, fmaf(a, e1, xv0 * sg));
            }
            {
                const float sg = s40.w * (1.0f - s40.w);
                const float a  = BETA * sg;
                const float e1 = fmaf(BETA, ew0.w, xv0);
                o1.w = fmaf(BETA, e1, xv0);
                o2.w = fmaf(a, rh0.w, fmaf(a, e1, xv0 * sg));
            }
            __stcs(&ew2[idx0], o1);
            __stcs(&rw2[idx0], o2);

            float4 p1, p2;
            {
                const float sg = s41.x * (1.0f - s41.x);
                const float a  = BETA * sg;
                const float e1 = fmaf(BETA, ew1.x, xv1);
                p1.x = fmaf(BETA, e1, xv1);
                p2.x = fmaf(a, rh1.x, fmaf(a, e1, xv1 * sg));
            }
            {
                const float sg = s41.y * (1.0f - s41.y);
                const float a  = BETA * sg;
                const float e1 = fmaf(BETA, ew1.y, xv1);
                p1.y = fmaf(BETA, e1, xv1);
                p2.y = fmaf(a, rh1.y, fmaf(a, e1, xv1 * sg));
            }
            {
                const float sg = s41.z * (1.0f - s41.z);
                const float a  = BETA * sg;
                const float e1 = fmaf(BETA, ew1.z, xv1);
                p1.z = fmaf(BETA, e1, xv1);
                p2.z = fmaf(a, rh1.z, fmaf(a, e1, xv1 * sg));
            }
            {
                const float sg = s41.w * (1.0f - s41.w);
                const float a  = BETA * sg;
                const float e1 = fmaf(BETA, ew1.w, xv1);
                p1.w = fmaf(BETA, e1, xv1);
                p2.w = fmaf(a, rh1.w, fmaf(a, e1, xv1 * sg));
            }
            __stcs(&ew2[idx1], p1);
            __stcs(&rw2[idx1], p2);
        }
    }
}

extern "C" void kernel_launch(void* const* d_in, const int* in_sizes, int n_in,
                              void* d_out, int out_size) {
    const float* x     = (const float*)d_in[0];
    const float* W     = (const float*)d_in[1];
    const float* bias  = (const float*)d_in[2];
    const float* u     = (const float*)d_in[3];
    const float* E_W   = (const float*)d_in[4];
    const float* E_b   = (const float*)d_in[5];
    const float* Rh_W  = (const float*)d_in[6];
    const float* Rh_b  = (const float*)d_in[7];
    const float* g_bar = (const float*)d_in[8];
    const float* r     = (const float*)d_in[9];
    float* out = (float*)d_out;

    fused_all<<<GRIDN, NTHR>>>(x, W, bias, u, (const float4*)E_W, E_b,
                               (const float4*)Rh_W, Rh_b, g_bar, r, out);
}

// round 13
// speedup vs baseline: 1.0904x; 1.0904x over previous
#include <cuda_runtime.h>
#include <math.h>

#define BB 32
#define DIN 1024
#define DOUT 1024
#define BETA 0.9f
#define LEAK 0.9f

#define GRIDN 512
#define NTHR 256

#define KTILE 16
#define NSPLIT (DIN / KTILE)   /* 64 */

/* output offsets (floats), in reference return order:
   s, E_W2, E_b2, Rh_W2, Rh_b2, g_bar2, r2 */
#define OFF_S  0
#define OFF_EW (BB * DOUT)
#define OFF_EB (OFF_EW + BB * DIN * DOUT)
#define OFF_RW (OFF_EB + BB * DOUT)
#define OFF_RB (OFF_RW + BB * DIN * DOUT)
#define OFF_G  (OFF_RB + BB * DOUT)
#define OFF_R  (OFF_G + BB * DOUT)

__device__ float g_hpart[NSPLIT][BB * DOUT];   /* 8 MB scratch */
__device__ unsigned int g_c1;                  /* monotonic barrier counter */

/* wrap-safe, reset-free grid barrier (2^32 % 512 == 0). */
__device__ __forceinline__ void grid_sync(unsigned int* cnt) {
    __syncthreads();
    if (threadIdx.x == 0) {
        __threadfence();
        const unsigned int prev = atomicAdd(cnt, 1u);
        const unsigned int target = prev - (prev % GRIDN) + GRIDN;
        volatile unsigned int* vc = (volatile unsigned int*)cnt;
        while ((int)(*vc - target) < 0) { __nanosleep(64); }
        __threadfence();
    }
    __syncthreads();
}

/* ---------- kernel 1: fused GEMM + activation + small outputs ---------- */
__global__ void __launch_bounds__(NTHR, 4)
fused_prologue(const float* __restrict__ x,
               const float* __restrict__ W,
               const float* __restrict__ bias,
               const float* __restrict__ u,
               const float* __restrict__ E_b,
               const float* __restrict__ Rh_b,
               const float* __restrict__ g_bar,
               const float* __restrict__ r,
               float* __restrict__ out) {
    __shared__ float ws[KTILE][128];   /* 8 KB: W tile 16k x 128j */
    __shared__ float xs[BB][KTILE];    /* 2 KB: x tile 32b x 16k */

    const int bid = blockIdx.x;
    const int tid = threadIdx.x;

    /* ---- Phase A: split-K GEMM, (jt, ks) = (8 x 64) over 512 blocks ---- */
    {
        const int jt = bid & 7;
        const int ks = bid >> 3;
        const int k0 = ks * KTILE;
        const int jb = jt * 128;

        /* W tile: 512 float4, 2 per thread */
        {
            int f = tid;
            int row = f >> 5, c4 = (f & 31) * 4;
            *(float4*)&ws[row][c4] = *(const float4*)&W[(k0 + row) * DOUT + jb + c4];
            f = tid + 256;
            row = f >> 5; c4 = (f & 31) * 4;
            *(float4*)&ws[row][c4] = *(const float4*)&W[(k0 + row) * DOUT + jb + c4];
        }
        /* x tile: 128 float4, 1 per thread (tid < 128) */
        if (tid < 128) {
            const int bb = tid >> 2;
            const int kq = (tid & 3) * 4;
            const float4 v = *(const float4*)&x[bb * DIN + k0 + kq];
            xs[bb][kq + 0] = v.x;
            xs[bb][kq + 1] = v.y;
            xs[bb][kq + 2] = v.z;
            xs[bb][kq + 3] = v.w;
        }
        __syncthreads();

        const int j4l = (tid & 31) * 4;
        const int bq  = tid >> 5;

        float4 a0 = make_float4(0.f, 0.f, 0.f, 0.f);
        float4 a1 = a0, a2 = a0, a3 = a0;

#pragma unroll
        for (int kk = 0; kk < KTILE; kk++) {
            const float4 w = *(const float4*)&ws[kk][j4l];
            const float x0 = xs[bq * 4 + 0][kk];
            const float x1 = xs[bq * 4 + 1][kk];
            const float x2 = xs[bq * 4 + 2][kk];
            const float x3 = xs[bq * 4 + 3][kk];
            a0.x = fmaf(x0, w.x, a0.x); a0.y = fmaf(x0, w.y, a0.y);
            a0.z = fmaf(x0, w.z, a0.z); a0.w = fmaf(x0, w.w, a0.w);
            a1.x = fmaf(x1, w.x, a1.x); a1.y = fmaf(x1, w.y, a1.y);
            a1.z = fmaf(x1, w.z, a1.z); a1.w = fmaf(x1, w.w, a1.w);
            a2.x = fmaf(x2, w.x, a2.x); a2.y = fmaf(x2, w.y, a2.y);
            a2.z = fmaf(x2, w.z, a2.z); a2.w = fmaf(x2, w.w, a2.w);
            a3.x = fmaf(x3, w.x, a3.x); a3.y = fmaf(x3, w.y, a3.y);
            a3.z = fmaf(x3, w.z, a3.z); a3.w = fmaf(x3, w.w, a3.w);
        }

        float* dst = &g_hpart[ks][0];
        *(float4*)&dst[(bq * 4 + 0) * DOUT + jb + j4l] = a0;
        *(float4*)&dst[(bq * 4 + 1) * DOUT + jb + j4l] = a1;
        *(float4*)&dst[(bq * 4 + 2) * DOUT + jb + j4l] = a2;
        *(float4*)&dst[(bq * 4 + 3) * DOUT + jb + j4l] = a3;
    }

    grid_sync(&g_c1);

    /* ---- Phase B: activation + small outputs (16 float4 items/block) ---- */
    if (tid < 16) {
        const int idx4 = bid * 16 + tid;      /* 0..8191 */
        const int bb = idx4 >> 8;
        const int j4 = idx4 & 255;

        float4 h = ((const float4*)bias)[j4];
#pragma unroll 8
        for (int ks = 0; ks < NSPLIT; ks++) {
            const float4 p = __ldcg(&((const float4*)g_hpart[ks])[idx4]);
            h.x += p.x; h.y += p.y; h.z += p.z; h.w += p.w;
        }

        const float4 uu = ((const float4*)u)[idx4];
        const float4 eb = ((const float4*)E_b)[idx4];
        const float4 rb = ((const float4*)Rh_b)[idx4];
        const float4 gb = ((const float4*)g_bar)[idx4];

        const float ratio0 = LEAK * r[bb];
        const float r2 = ratio0 + 1.0f;
        const float ratio = ratio0 / r2;

        float4 so, ebo, rbo, go;
        {
            const float un = BETA * uu.x + h.x;
            const float s  = 1.0f / (1.0f + expf(-(un - 1.0f)));
            const float sg = s * (1.0f - s);
            const float a  = BETA * sg;
            so.x = s;
            const float eb1 = BETA * eb.x + 1.0f;
            ebo.x = BETA * eb1 + 1.0f;
            rbo.x = a * rb.x + (a * eb1 + sg);
            go.x  = ratio * gb.x + (1.0f - ratio) * a;
        }
        {
            const float un = BETA * uu.y + h.y;
            const float s  = 1.0f / (1.0f + expf(-(un - 1.0f)));
            const float sg = s * (1.0f - s);
            const float a  = BETA * sg;
            so.y = s;
            const float eb1 = BETA * eb.y + 1.0f;
            ebo.y = BETA * eb1 + 1.0f;
            rbo.y = a * rb.y + (a * eb1 + sg);
            go.y  = ratio * gb.y + (1.0f - ratio) * a;
        }
        {
            const float un = BETA * uu.z + h.z;
            const float s  = 1.0f / (1.0f + expf(-(un - 1.0f)));
            const float sg = s * (1.0f - s);
            const float a  = BETA * sg;
            so.z = s;
            const float eb1 = BETA * eb.z + 1.0f;
            ebo.z = BETA * eb1 + 1.0f;
            rbo.z = a * rb.z + (a * eb1 + sg);
            go.z  = ratio * gb.z + (1.0f - ratio) * a;
        }
        {
            const float un = BETA * uu.w + h.w;
            const float s  = 1.0f / (1.0f + expf(-(un - 1.0f)));
            const float sg = s * (1.0f - s);
            const float a  = BETA * sg;
            so.w = s;
            const float eb1 = BETA * eb.w + 1.0f;
            ebo.w = BETA * eb1 + 1.0f;
            rbo.w = a * rb.w + (a * eb1 + sg);
            go.w  = ratio * gb.w + (1.0f - ratio) * a;
        }

        ((float4*)(out + OFF_S))[idx4]  = so;
        ((float4*)(out + OFF_EB))[idx4] = ebo;
        ((float4*)(out + OFF_RB))[idx4] = rbo;
        ((float4*)(out + OFF_G))[idx4]  = go;
        if (j4 == 0) out[OFF_R + bb] = r2;
    }
}

/* ---------------- kernel 2: big streaming trace update ----------------- */
/* Flat 32768-block launch, one float4 pair per thread — the shape that
   reliably hits ~6.4 TB/s. */
__global__ void __launch_bounds__(256) big_update(const float* __restrict__ x,
                                                  const float4* __restrict__ E_W,
                                                  const float4* __restrict__ Rh_W,
                                                  float* __restrict__ out) {
    const float4* __restrict__ s4p = (const float4*)(out + OFF_S);
    float4* __restrict__ ew2 = (float4*)(out + OFF_EW);
    float4* __restrict__ rw2 = (float4*)(out + OFF_RW);

    const int idx = blockIdx.x * 256 + threadIdx.x;   /* 0..8388607 */
    const int bb  = idx >> 18;
    const int rem = idx & 262143;
    const int i   = rem >> 8;
    const int j4  = rem & 255;

    const float4 ew = __ldcs(&E_W[idx]);
    const float4 rh = __ldcs(&Rh_W[idx]);
    const float  xv = __ldg(&x[bb * DIN + i]);
    const float4 s4 = s4p[bb * 256 + j4];

    float4 o1, o2;

    {
        const float sg = s4.x * (1.0f - s4.x);
        const float a  = BETA * sg;
        const float e1 = fmaf(BETA, ew.x, xv);
        o1.x = fmaf(BETA, e1, xv);
        o2.x = fmaf(a, rh.x, fmaf(a, e1, xv * sg));
    }
    {
        const float sg = s4.y * (1.0f - s4.y);
        const float a  = BETA * sg;
        const float e1 = fmaf(BETA, ew.y, xv);
        o1.y = fmaf(BETA, e1, xv);
        o2.y = fmaf(a, rh.y, fmaf(a, e1, xv * sg));
    }
    {
        const float sg = s4.z * (1.0f - s4.z);
        const float a  = BETA * sg;
        const float e1 = fmaf(BETA, ew.z, xv);
        o1.z = fmaf(BETA, e1, xv);
        o2.z = fmaf(a, rh.z, fmaf(a, e1, xv * sg));
    }
    {
        const float sg = s4.w * (1.0f - s4.w);
        const float a  = BETA * sg;
        const float e1 = fmaf(BETA, ew.w, xv);
        o1.w = fmaf(BETA, e1, xv);
        o2.w = fmaf(a, rh.w, fmaf(a, e1, xv * sg));
    }

    __stcs(&ew2[idx], o1);
    __stcs(&rw2[idx], o2);
}

extern "C" void kernel_launch(void* const* d_in, const int* in_sizes, int n_in,
                              void* d_out, int out_size) {
    const float* x     = (const float*)d_in[0];
    const float* W     = (const float*)d_in[1];
    const float* bias  = (const float*)d_in[2];
    const float* u     = (const float*)d_in[3];
    const float* E_W   = (const float*)d_in[4];
    const float* E_b   = (const float*)d_in[5];
    const float* Rh_W  = (const float*)d_in[6];
    const float* Rh_b  = (const float*)d_in[7];
    const float* g_bar = (const float*)d_in[8];
    const float* r     = (const float*)d_in[9];
    float* out = (float*)d_out;

    fused_prologue<<<GRIDN, NTHR>>>(x, W, bias, u, E_b, Rh_b, g_bar, r, out);
    big_update<<<(BB * DIN * DOUT / 4) / 256, 256>>>(x, (const float4*)E_W,
                                                     (const float4*)Rh_W, out);
}